// round 1
// baseline (speedup 1.0000x reference)
#include <cuda_runtime.h>
#include <cuda_bf16.h>

// Block-diagonal Hadamard rotation via Fast Walsh-Hadamard Transform.
// x: [8192*8192] f32 viewed as 512K rows of 128. Each 128-row -> FWHT -> *1/sqrt(128).
// One warp handles one 128-element block: lane l holds elements [4l, 4l+3] (float4).
// Element index bits: q (bits 0-1) intra-thread, lane (bits 2-6) via shfl.xor.

#define FWHT_SCALE 0.088388347648318447f  // 1/sqrt(128)

__global__ void __launch_bounds__(256) hadamard_fwht_kernel(
    const float4* __restrict__ in, float4* __restrict__ out, int n4)
{
    int idx = blockIdx.x * blockDim.x + threadIdx.x;
    if (idx >= n4) return;

    // Streaming load (no reuse; avoid L2 pollution)
    float4 v = __ldcs(&in[idx]);

    // ---- intra-thread stages (element bits 0 and 1) ----
    // bit 0: pairs (x,y), (z,w)
    float a0 = v.x + v.y;
    float a1 = v.x - v.y;
    float a2 = v.z + v.w;
    float a3 = v.z - v.w;
    // bit 1: pairs (0,2), (1,3)
    float b0 = a0 + a2;
    float b1 = a1 + a3;
    float b2 = a0 - a2;
    float b3 = a1 - a3;

    // ---- cross-lane stages (element bits 2..6 == lane bits 0..4) ----
    const unsigned FULL = 0xFFFFFFFFu;
    #pragma unroll
    for (int m = 1; m <= 16; m <<= 1) {
        float t0 = __shfl_xor_sync(FULL, b0, m);
        float t1 = __shfl_xor_sync(FULL, b1, m);
        float t2 = __shfl_xor_sync(FULL, b2, m);
        float t3 = __shfl_xor_sync(FULL, b3, m);
        // low lane of pair: sum; high lane: (partner - mine) = low - high
        bool hi = (threadIdx.x & m) != 0;
        float s = hi ? -1.0f : 1.0f;
        b0 = fmaf(b0, s, t0);
        b1 = fmaf(b1, s, t1);
        b2 = fmaf(b2, s, t2);
        b3 = fmaf(b3, s, t3);
    }

    float4 r;
    r.x = b0 * FWHT_SCALE;
    r.y = b1 * FWHT_SCALE;
    r.z = b2 * FWHT_SCALE;
    r.w = b3 * FWHT_SCALE;
    __stcs(&out[idx], r);
}

extern "C" void kernel_launch(void* const* d_in, const int* in_sizes, int n_in,
                              void* d_out, int out_size) {
    const float* x = (const float*)d_in[0];
    // d_in[1] is W (128x128) — unused: FWHT computes the same transform.
    float* o = (float*)d_out;

    int n = in_sizes[0];          // 8192*8192 = 67,108,864 (multiple of 128)
    int n4 = n >> 2;              // float4 count, multiple of 32 per warp-block
    int threads = 256;
    int blocks = (n4 + threads - 1) / threads;

    hadamard_fwht_kernel<<<blocks, threads>>>(
        (const float4*)x, (float4*)o, n4);
}

// round 3
// speedup vs baseline: 1.0501x; 1.0501x over previous
#include <cuda_runtime.h>
#include <cuda_bf16.h>

// Block-diagonal Hadamard rotation via Fast Walsh-Hadamard Transform (FWHT).
// x viewed as 512K rows of 128; each row -> FWHT -> * 1/sqrt(128).
//
// Layout: 16 elements per thread. 8-lane group owns one 128-block.
//   element index e = q + 4*l + 32*j   (q=bits0-1 intra-float4, l=lane%8 -> bits2-4,
//                                       j=0..3 register-quad -> bits5-6)
//   thread register index i = 4*j + q  -> intra-thread butterfly over i bits 0..3
//   lane bits 0..2 -> 3 shfl.xor stages (masks 1,2,4 stay within 8-lane groups)
//
// Loads: float4 idx = (t>>3)*32 + (t&7) + 8*j -> per group, 8 consecutive float4s
// = 128B contiguous per load per group; fully coalesced. MLP=4 per thread.

#define FWHT_SCALE 0.088388347648318447f  // 1/sqrt(128)

__global__ void __launch_bounds__(256) hadamard_fwht16_kernel(
    const float4* __restrict__ in, float4* __restrict__ out, int nthreads)
{
    int t = blockIdx.x * blockDim.x + threadIdx.x;
    if (t >= nthreads) return;

    int base = ((t >> 3) << 5) + (t & 7);   // (t/8)*32 + t%8

    float x[16];
    #pragma unroll
    for (int j = 0; j < 4; j++) {
        float4 v = __ldcs(&in[base + 8 * j]);
        x[4 * j + 0] = v.x;
        x[4 * j + 1] = v.y;
        x[4 * j + 2] = v.z;
        x[4 * j + 3] = v.w;
    }

    // ---- intra-thread butterflies: element bits 0,1 (q) and 5,6 (j)
    //      == butterfly over register-index bits 0..3 ----
    #pragma unroll
    for (int s = 1; s < 16; s <<= 1) {
        #pragma unroll
        for (int i = 0; i < 16; i++) {
            if (!(i & s)) {
                float a = x[i];
                float b = x[i ^ s];
                x[i]     = a + b;
                x[i ^ s] = a - b;
            }
        }
    }

    // ---- cross-lane butterflies: element bits 2..4 == lane bits 0..2 ----
    const unsigned FULL = 0xFFFFFFFFu;
    int lane = threadIdx.x & 31;
    #pragma unroll
    for (int m = 1; m <= 4; m <<= 1) {
        float s = (lane & m) ? -1.0f : 1.0f;
        #pragma unroll
        for (int i = 0; i < 16; i++) {
            float p = __shfl_xor_sync(FULL, x[i], m);
            x[i] = fmaf(x[i], s, p);
        }
    }

    #pragma unroll
    for (int j = 0; j < 4; j++) {
        float4 r;
        r.x = x[4 * j + 0] * FWHT_SCALE;
        r.y = x[4 * j + 1] * FWHT_SCALE;
        r.z = x[4 * j + 2] * FWHT_SCALE;
        r.w = x[4 * j + 3] * FWHT_SCALE;
        __stcs(&out[base + 8 * j], r);
    }
}

extern "C" void kernel_launch(void* const* d_in, const int* in_sizes, int n_in,
                              void* d_out, int out_size) {
    const float* x = (const float*)d_in[0];
    // d_in[1] is W (128x128) — unused: FWHT computes the identical transform.
    float* o = (float*)d_out;

    int n = in_sizes[0];            // 67,108,864 elements (multiple of 512)
    int nthreads = n >> 4;          // 16 elements per thread
    int threads = 256;
    int blocks = (nthreads + threads - 1) / threads;

    hadamard_fwht16_kernel<<<blocks, threads>>>(
        (const float4*)x, (float4*)o, nthreads);
}